// round 1
// baseline (speedup 1.0000x reference)
#include <cuda_runtime.h>
#include <math.h>

#define T_TOK 2048
#define DDIM  2048
#define FDIM  4096
#define NEXP  8

#define BM 64
#define BN 64
#define BK 16
#define NTHREADS 128

// ---- static scratch (no allocations allowed) ----
__device__ int   g_count[NEXP];
__device__ int   g_list[NEXP * T_TOK];
__device__ int   g_eidx[T_TOK];
__device__ float g_wgt[T_TOK];
__device__ float g_h[(size_t)T_TOK * FDIM];   // [T, F] intermediate

__global__ void zero_counts() {
    if (threadIdx.x < NEXP) g_count[threadIdx.x] = 0;
}

// one warp per token: logits = x[t] @ rw, top-1 + sigmoid
__global__ void router_kernel(const float* __restrict__ x,
                              const float* __restrict__ rw) {
    int t = blockIdx.x * blockDim.y + threadIdx.y;
    if (t >= T_TOK) return;
    int lane = threadIdx.x;
    float acc[NEXP];
#pragma unroll
    for (int e = 0; e < NEXP; e++) acc[e] = 0.f;
    const float* xr = x + (size_t)t * DDIM;
    for (int d = lane; d < DDIM; d += 32) {
        float xv = xr[d];
        const float4* r = (const float4*)(rw + (size_t)d * NEXP);
        float4 r0 = r[0], r1 = r[1];
        acc[0] += xv * r0.x; acc[1] += xv * r0.y;
        acc[2] += xv * r0.z; acc[3] += xv * r0.w;
        acc[4] += xv * r1.x; acc[5] += xv * r1.y;
        acc[6] += xv * r1.z; acc[7] += xv * r1.w;
    }
#pragma unroll
    for (int off = 16; off > 0; off >>= 1) {
#pragma unroll
        for (int e = 0; e < NEXP; e++)
            acc[e] += __shfl_down_sync(0xffffffffu, acc[e], off);
    }
    if (lane == 0) {
        int best = 0; float bv = acc[0];
#pragma unroll
        for (int e = 1; e < NEXP; e++)
            if (acc[e] > bv) { bv = acc[e]; best = e; }
        g_eidx[t] = best;
        g_wgt[t]  = 1.f / (1.f + expf(-bv));
    }
}

__global__ void scatter_kernel() {
    int t = blockIdx.x * blockDim.x + threadIdx.x;
    if (t < T_TOK) {
        int e = g_eidx[t];
        int p = atomicAdd(&g_count[e], 1);
        g_list[e * T_TOK + p] = t;
    }
}

__device__ __forceinline__ float silu_f(float g) {
    return g / (1.f + expf(-g));
}

// h[tok, n] = silu(x[tok] @ Wg[:,n]) * (x[tok] @ Wu[:,n]) for tokens of expert e
template<bool SHARED>
__global__ void __launch_bounds__(NTHREADS)
gateup_kernel(const float* __restrict__ x,
              const float* __restrict__ wg,
              const float* __restrict__ wu) {
    int e   = SHARED ? 0 : blockIdx.z;
    int cnt = SHARED ? T_TOK : g_count[e];
    int m0  = blockIdx.y * BM;
    if (m0 >= cnt) return;
    int n0  = blockIdx.x * BN;
    const float* wgb = wg + (SHARED ? 0 : (size_t)e * DDIM * FDIM);
    const float* wub = wu + (SHARED ? 0 : (size_t)e * DDIM * FDIM);

    __shared__ float As[BK][BM + 4];
    __shared__ float Bg[BK][BN];
    __shared__ float Bu[BK][BN];
    __shared__ int   toks[BM];

    int tid = threadIdx.x;
    if (tid < BM) {
        int m = m0 + tid;
        toks[tid] = (m < cnt) ? (SHARED ? m : g_list[e * T_TOK + m]) : -1;
    }
    __syncthreads();

    float accg[8][4], accu[8][4];
#pragma unroll
    for (int i = 0; i < 8; i++)
#pragma unroll
        for (int j = 0; j < 4; j++) { accg[i][j] = 0.f; accu[i][j] = 0.f; }

    int tr = tid >> 4;   // 0..7 -> rows tr*8..tr*8+7
    int tc = tid & 15;   // 0..15 -> cols tc*4..tc*4+3

    for (int k0 = 0; k0 < DDIM; k0 += BK) {
        // A tile: 64 rows x 16 k, gathered by token id, stored transposed
#pragma unroll
        for (int it = 0; it < 2; it++) {
            int s   = tid * 2 + it;      // 0..255 float4 slots
            int row = s >> 2;            // 0..63
            int q   = s & 3;             // 0..3 (quad of 4 floats)
            int tk  = toks[row];
            float4 v = make_float4(0.f, 0.f, 0.f, 0.f);
            if (tk >= 0)
                v = *(const float4*)(x + (size_t)tk * DDIM + k0 + q * 4);
            As[q * 4 + 0][row] = v.x; As[q * 4 + 1][row] = v.y;
            As[q * 4 + 2][row] = v.z; As[q * 4 + 3][row] = v.w;
        }
        // B tiles: 16 k-rows x 64 n
#pragma unroll
        for (int it = 0; it < 2; it++) {
            int s  = tid * 2 + it;
            int kr = s >> 4;             // 0..15
            int q  = s & 15;             // 0..15
            size_t off = (size_t)(k0 + kr) * FDIM + n0 + q * 4;
            *(float4*)&Bg[kr][q * 4] = *(const float4*)(wgb + off);
            *(float4*)&Bu[kr][q * 4] = *(const float4*)(wub + off);
        }
        __syncthreads();
#pragma unroll
        for (int k = 0; k < BK; k++) {
            float a[8];
            *(float4*)&a[0] = *(const float4*)&As[k][tr * 8];
            *(float4*)&a[4] = *(const float4*)&As[k][tr * 8 + 4];
            float4 bg = *(const float4*)&Bg[k][tc * 4];
            float4 bu = *(const float4*)&Bu[k][tc * 4];
#pragma unroll
            for (int i = 0; i < 8; i++) {
                accg[i][0] += a[i] * bg.x; accg[i][1] += a[i] * bg.y;
                accg[i][2] += a[i] * bg.z; accg[i][3] += a[i] * bg.w;
                accu[i][0] += a[i] * bu.x; accu[i][1] += a[i] * bu.y;
                accu[i][2] += a[i] * bu.z; accu[i][3] += a[i] * bu.w;
            }
        }
        __syncthreads();
    }

#pragma unroll
    for (int i = 0; i < 8; i++) {
        int tk = toks[tr * 8 + i];
        if (tk < 0) continue;
        float4 o;
        o.x = silu_f(accg[i][0]) * accu[i][0];
        o.y = silu_f(accg[i][1]) * accu[i][1];
        o.z = silu_f(accg[i][2]) * accu[i][2];
        o.w = silu_f(accg[i][3]) * accu[i][3];
        *(float4*)(g_h + (size_t)tk * FDIM + n0 + tc * 4) = o;
    }
}

// out[tok, n] (+)= wgt * (h[tok] @ Wd[:, n])
template<bool SHARED>
__global__ void __launch_bounds__(NTHREADS)
down_kernel(const float* __restrict__ wd, float* __restrict__ out) {
    int e   = SHARED ? 0 : blockIdx.z;
    int cnt = SHARED ? T_TOK : g_count[e];
    int m0  = blockIdx.y * BM;
    if (m0 >= cnt) return;
    int n0  = blockIdx.x * BN;
    const float* wdb = wd + (SHARED ? 0 : (size_t)e * FDIM * DDIM);

    __shared__ float As[BK][BM + 4];
    __shared__ float Bs[BK][BN];
    __shared__ int   toks[BM];

    int tid = threadIdx.x;
    if (tid < BM) {
        int m = m0 + tid;
        toks[tid] = (m < cnt) ? (SHARED ? m : g_list[e * T_TOK + m]) : -1;
    }
    __syncthreads();

    float acc[8][4];
#pragma unroll
    for (int i = 0; i < 8; i++)
#pragma unroll
        for (int j = 0; j < 4; j++) acc[i][j] = 0.f;

    int tr = tid >> 4;
    int tc = tid & 15;

    for (int k0 = 0; k0 < FDIM; k0 += BK) {
#pragma unroll
        for (int it = 0; it < 2; it++) {
            int s   = tid * 2 + it;
            int row = s >> 2;
            int q   = s & 3;
            int tk  = toks[row];
            float4 v = make_float4(0.f, 0.f, 0.f, 0.f);
            if (tk >= 0)
                v = *(const float4*)(g_h + (size_t)tk * FDIM + k0 + q * 4);
            As[q * 4 + 0][row] = v.x; As[q * 4 + 1][row] = v.y;
            As[q * 4 + 2][row] = v.z; As[q * 4 + 3][row] = v.w;
        }
#pragma unroll
        for (int it = 0; it < 2; it++) {
            int s  = tid * 2 + it;
            int kr = s >> 4;
            int q  = s & 15;
            size_t off = (size_t)(k0 + kr) * DDIM + n0 + q * 4;
            *(float4*)&Bs[kr][q * 4] = *(const float4*)(wdb + off);
        }
        __syncthreads();
#pragma unroll
        for (int k = 0; k < BK; k++) {
            float a[8];
            *(float4*)&a[0] = *(const float4*)&As[k][tr * 8];
            *(float4*)&a[4] = *(const float4*)&As[k][tr * 8 + 4];
            float4 b = *(const float4*)&Bs[k][tc * 4];
#pragma unroll
            for (int i = 0; i < 8; i++) {
                acc[i][0] += a[i] * b.x; acc[i][1] += a[i] * b.y;
                acc[i][2] += a[i] * b.z; acc[i][3] += a[i] * b.w;
            }
        }
        __syncthreads();
    }

#pragma unroll
    for (int i = 0; i < 8; i++) {
        int tk = toks[tr * 8 + i];
        if (tk < 0) continue;
        float s = SHARED ? 1.f : g_wgt[tk];
        float* op = out + (size_t)tk * DDIM + n0 + tc * 4;
        float4 o;
        o.x = s * acc[i][0]; o.y = s * acc[i][1];
        o.z = s * acc[i][2]; o.w = s * acc[i][3];
        if (SHARED) {
            float4 p = *(float4*)op;
            o.x += p.x; o.y += p.y; o.z += p.z; o.w += p.w;
        }
        *(float4*)op = o;
    }
}

extern "C" void kernel_launch(void* const* d_in, const int* in_sizes, int n_in,
                              void* d_out, int out_size) {
    const float* x   = (const float*)d_in[0];
    const float* rw  = (const float*)d_in[1];
    const float* wg  = (const float*)d_in[2];
    const float* wu  = (const float*)d_in[3];
    const float* wd  = (const float*)d_in[4];
    const float* wsg = (const float*)d_in[5];
    const float* wsu = (const float*)d_in[6];
    const float* wsd = (const float*)d_in[7];
    float* out = (float*)d_out;

    zero_counts<<<1, 32>>>();
    router_kernel<<<T_TOK / 8, dim3(32, 8)>>>(x, rw);
    scatter_kernel<<<T_TOK / 256, 256>>>();

    // routed experts: gate/up -> h, then down -> out (writes every token once)
    dim3 g1(FDIM / BN, T_TOK / BM, NEXP);
    gateup_kernel<false><<<g1, NTHREADS>>>(x, wg, wu);
    dim3 g2(DDIM / BN, T_TOK / BM, NEXP);
    down_kernel<false><<<g2, NTHREADS>>>(wd, out);

    // shared expert: gate/up -> h (reuse), then down += out
    dim3 g3(FDIM / BN, T_TOK / BM, 1);
    gateup_kernel<true><<<g3, NTHREADS>>>(x, wsg, wsu);
    dim3 g4(DDIM / BN, T_TOK / BM, 1);
    down_kernel<true><<<g4, NTHREADS>>>(wsd, out);
}